// round 12
// baseline (speedup 1.0000x reference)
#include <cuda_runtime.h>
#include <cstdint>
#include <cstddef>

#define B_  16
#define L_  2048
#define C_  128
#define U_  40
#define GJ  4
#define NTHA 512
#define NTHB 128
#define NCHUNK 4
#define CCHUNK (C_ / NCHUNK)   // 32

#define NEG_INF __int_as_float(0xff800000)
#define POS_INF __int_as_float(0x7f800000)

// scratch (device globals: no allocation allowed)
__device__ float g_xT[B_ * C_ * L_];
__device__ float g_outT[B_ * C_ * L_];
__device__ int4  g_isampT[(U_ / 4) * L_];   // [q][l]
__device__ float g_Mp[B_ * C_ * L_];        // planar M: [(b*C + c)][l]

// ---------------------------------------------------------------------------
// float4 batched transpose: src (NI, NJ) -> dst (NJ, NI), per batch z.
__global__ void transpose4_k(float* __restrict__ dst, const float* __restrict__ src,
                             int NI, int NJ) {
    __shared__ float tile[32][33];
    const int z = blockIdx.z;
    const float* s = src + (size_t)z * NI * NJ;
    float* d = dst + (size_t)z * NI * NJ;
    const int j0 = blockIdx.x * 32, i0 = blockIdx.y * 32;
    const int tx = threadIdx.x, ty = threadIdx.y;
    float4 v = *(const float4*)&s[(size_t)(i0 + ty) * NJ + j0 + tx * 4];
    tile[ty][tx * 4 + 0] = v.x;
    tile[ty][tx * 4 + 1] = v.y;
    tile[ty][tx * 4 + 2] = v.z;
    tile[ty][tx * 4 + 3] = v.w;
    __syncthreads();
    float4 o;
    o.x = tile[tx * 4 + 0][ty];
    o.y = tile[tx * 4 + 1][ty];
    o.z = tile[tx * 4 + 2][ty];
    o.w = tile[tx * 4 + 3][ty];
    *(float4*)&d[(size_t)(j0 + ty) * NI + i0 + tx * 4] = o;
}

// isamp (L x U ints) -> isampT[q][l] (10 x 2048 int4)
__global__ void transpose_idx(int4* __restrict__ dst, const int* __restrict__ src) {
    __shared__ int4 st[256 * (U_ / 4)];
    const int lb = blockIdx.x * 256;
    const int4* s = (const int4*)(src + (size_t)lb * U_);
    for (int i = threadIdx.x; i < 256 * (U_ / 4); i += 256) st[i] = s[i];
    __syncthreads();
#pragma unroll
    for (int q = 0; q < U_ / 4; q++)
        dst[q * L_ + lb + threadIdx.x] = st[threadIdx.x * (U_ / 4) + q];
}

__device__ __forceinline__ float fexp2(float x) {
    float y;
    asm("ex2.approx.ftz.f32 %0, %1;" : "=f"(y) : "f"(x));
    return y;
}

// ---- Blackwell packed f32x2 ops ---------------------------------------------
__device__ __forceinline__ float2 f2mul(float2 a, float2 b) {
    float2 r;
    asm("{\n\t.reg .b64 ra, rb, rc;\n\t"
        "mov.b64 ra, {%2, %3};\n\t"
        "mov.b64 rb, {%4, %5};\n\t"
        "mul.rn.f32x2 rc, ra, rb;\n\t"
        "mov.b64 {%0, %1}, rc;\n\t}"
        : "=f"(r.x), "=f"(r.y) : "f"(a.x), "f"(a.y), "f"(b.x), "f"(b.y));
    return r;
}
__device__ __forceinline__ float2 f2add(float2 a, float2 b) {
    float2 r;
    asm("{\n\t.reg .b64 ra, rb, rc;\n\t"
        "mov.b64 ra, {%2, %3};\n\t"
        "mov.b64 rb, {%4, %5};\n\t"
        "add.rn.f32x2 rc, ra, rb;\n\t"
        "mov.b64 {%0, %1}, rc;\n\t}"
        : "=f"(r.x), "=f"(r.y) : "f"(a.x), "f"(a.y), "f"(b.x), "f"(b.y));
    return r;
}
__device__ __forceinline__ float2 f2fma(float2 a, float2 b, float2 c) {
    float2 r;
    asm("{\n\t.reg .b64 ra, rb, rc, rd;\n\t"
        "mov.b64 ra, {%2, %3};\n\t"
        "mov.b64 rb, {%4, %5};\n\t"
        "mov.b64 rc, {%6, %7};\n\t"
        "fma.rn.f32x2 rd, ra, rb, rc;\n\t"
        "mov.b64 {%0, %1}, rd;\n\t}"
        : "=f"(r.x), "=f"(r.y)
        : "f"(a.x), "f"(a.y), "f"(b.x), "f"(b.y), "f"(c.x), "f"(c.y));
    return r;
}

#define GATH4(ii)                                                     \
    {                                                                 \
        float4 g = xs4[ii];                                           \
        float2 t01 = f2mul(A01, make_float2(g.x, g.y));               \
        float2 t23 = f2mul(A23, make_float2(g.z, g.w));               \
        gm0 = fmaxf(gm0, t01.x); gm1 = fmaxf(gm1, t01.y);             \
        gm2 = fmaxf(gm2, t23.x); gm3 = fmaxf(gm3, t23.y);             \
        gs01 = f2add(gs01, make_float2(g.x, g.y));                    \
        gs23 = f2add(gs23, make_float2(g.z, g.w));                    \
    }

// inner S4 body for one x value
#define S4BODY(xv)                                                    \
    {                                                                 \
        float2 xv2 = make_float2((xv), (xv));                         \
        float2 p01 = f2fma(a01, xv2, mn01);                           \
        float2 p23 = f2fma(a23, xv2, mn23);                           \
        float p4 = fmaf(a2[4], (xv), m2n[4]);                         \
        float2 e01 = make_float2(fexp2(p01.x), fexp2(p01.y));         \
        float2 e23 = make_float2(fexp2(p23.x), fexp2(p23.y));         \
        float e4 = fexp2(p4);                                         \
        s01 = f2add(s01, e01);                                        \
        s23 = f2add(s23, e23);                                        \
        s4 += e4;                                                     \
        sv01 = f2fma(e01, xv2, sv01);                                 \
        sv23 = f2fma(e23, xv2, sv23);                                 \
        sv4 = fmaf(e4, (xv), sv4);                                    \
    }

// ============================================================================
// K_A: measure. 4 batch columns -> M planar. smem 32KB, occ 4.
// ============================================================================
__global__ void __launch_bounds__(NTHA, 4)
informer_measure(const float* __restrict__ xT, float* __restrict__ Mp,
                 const int4* __restrict__ isampT, int c0,
                 const float* pWq, const float* pbq,
                 const float* pWk, const float* pbk) {
    const int c   = blockIdx.x + c0;
    const int b0  = blockIdx.y * GJ;
    const int tid = threadIdx.x;

    extern __shared__ float sm[];
    float4* xs4 = (float4*)sm;

    const float Wq = *pWq, bq = *pbq, Wk = *pWk, bk = *pbk;
    const float invL = 1.0f / (float)L_;

#pragma unroll
    for (int jj = 0; jj < GJ; jj++) {
        const float* row = xT + ((size_t)(b0 + jj) * C_ + c) * L_;
#pragma unroll
        for (int i = 0; i < L_ / NTHA; i++)
            ((float*)&xs4[tid + i * NTHA])[jj] = row[tid + i * NTHA];
    }
    __syncthreads();

    float* M0 = Mp + ((size_t)(b0 + 0) * C_ + c) * L_;
    float* M1 = Mp + ((size_t)(b0 + 1) * C_ + c) * L_;
    float* M2 = Mp + ((size_t)(b0 + 2) * C_ + c) * L_;
    float* M3 = Mp + ((size_t)(b0 + 3) * C_ + c) * L_;
#pragma unroll
    for (int i = 0; i < L_ / NTHA; i++) {
        int l = tid + i * NTHA;
        float4 xc = xs4[l];
        const float q0 = fmaf(Wq, xc.x, bq), q1 = fmaf(Wq, xc.y, bq);
        const float q2 = fmaf(Wq, xc.z, bq), q3 = fmaf(Wq, xc.w, bq);
        const float2 A01 = make_float2(q0 * Wk, q1 * Wk);
        const float2 A23 = make_float2(q2 * Wk, q3 * Wk);
        const float B00 = q0 * bk, B01 = q1 * bk, B02 = q2 * bk, B03 = q3 * bk;

        float gm0 = NEG_INF, gm1 = NEG_INF, gm2 = NEG_INF, gm3 = NEG_INF;
        float2 gs01 = make_float2(0.f, 0.f), gs23 = make_float2(0.f, 0.f);
#pragma unroll
        for (int q = 0; q < U_ / 4; q++) {
            int4 iv = __ldg(&isampT[q * L_ + l]);
            GATH4(iv.x) GATH4(iv.y) GATH4(iv.z) GATH4(iv.w)
        }
        M0[l] = (gm0 + B00) - fmaf(A01.x, gs01.x, (float)U_ * B00) * invL;
        M1[l] = (gm1 + B01) - fmaf(A01.y, gs01.y, (float)U_ * B01) * invL;
        M2[l] = (gm2 + B02) - fmaf(A23.x, gs23.x, (float)U_ * B02) * invL;
        M3[l] = (gm3 + B03) - fmaf(A23.y, gs23.y, (float)U_ * B03) * invL;
    }
}

// ============================================================================
// K_B: attention. one CTA per (b, c). 128 threads, smem ~17KB.
// ============================================================================
static constexpr int SMB_XC   = 0;
static constexpr int SMB_MC   = SMB_XC + L_;
static constexpr int SMB_UPD  = SMB_MC + L_;          // U
static constexpr int SMB_TOP  = SMB_UPD + U_;         // U (int)
static constexpr int SMB_SLOTV= SMB_TOP + U_;         // 8
static constexpr int SMB_SLOTI= SMB_SLOTV + 8;        // 8
static constexpr int SMB_R    = SMB_SLOTI + 8;        // 16
static constexpr int SMB_TOTAL = SMB_R + 16;
static constexpr size_t SMEMB_BYTES = (size_t)SMB_TOTAL * 4;

__global__ void __launch_bounds__(NTHB, 12)
informer_attn(const float* __restrict__ xT, float* __restrict__ outT,
              const float* __restrict__ Mp, int c0,
              const float* pWq, const float* pbq, const float* pWk, const float* pbk,
              const float* pWv, const float* pbv, const float* pWo, const float* pbo,
              const float* pw1, const float* pb1, const float* pw2, const float* pb2,
              const float* pg1, const float* pbe1, const float* pg2, const float* pbe2) {
    const int c    = blockIdx.x + c0;
    const int b    = blockIdx.y;
    const int tid  = threadIdx.x;
    const int lane = tid & 31, warp = tid >> 5;

    extern __shared__ float sm[];
    float* xc    = sm + SMB_XC;
    float* Mc    = sm + SMB_MC;
    float* sUpd  = sm + SMB_UPD;
    int*   sTop  = (int*)(sm + SMB_TOP);
    float* slotV = sm + SMB_SLOTV;
    int*   slotI = (int*)(sm + SMB_SLOTI);
    float* sR    = sm + SMB_R;

    const float invL = 1.0f / (float)L_;
    const float Wq = *pWq, bq = *pbq, Wk = *pWk;
    const float Wv = *pWv, bvc = *pbv;

    // ---- load column + M, compute stats ----
    {
        const float* xrow = xT + ((size_t)b * C_ + c) * L_;
        const float* Mrow = Mp + ((size_t)b * C_ + c) * L_;
        float lmax = NEG_INF, lmin = POS_INF, lsum = 0.f;
#pragma unroll
        for (int i = 0; i < L_ / NTHB; i++) {
            int l = tid + i * NTHB;
            float x = xrow[l];
            xc[l] = x;
            Mc[l] = Mrow[l];
            lmax = fmaxf(lmax, x);
            lmin = fminf(lmin, x);
            lsum += x;
        }
#pragma unroll
        for (int o = 16; o; o >>= 1) {
            lmax = fmaxf(lmax, __shfl_xor_sync(0xffffffffu, lmax, o));
            lmin = fminf(lmin, __shfl_xor_sync(0xffffffffu, lmin, o));
            lsum += __shfl_xor_sync(0xffffffffu, lsum, o);
        }
        if (lane == 0) {
            sR[warp * 3 + 0] = lmax;
            sR[warp * 3 + 1] = lmin;
            sR[warp * 3 + 2] = lsum;
        }
        __syncthreads();
    }
    const float xmx = fmaxf(fmaxf(sR[0], sR[3]), fmaxf(sR[6], sR[9]));
    const float xmn = fminf(fminf(sR[1], sR[4]), fminf(sR[7], sR[10]));
    const float xsum = sR[2] + sR[5] + sR[8] + sR[11];
    const float vmean = fmaf(Wv, xsum * invL, bvc);
    __syncthreads();

    // ---- S3: top-U, stripe top-2 cache + removal mask ----
    {
        float v0 = NEG_INF, v1 = NEG_INF;
        int i0 = 0, i1 = 0;
        unsigned rm = 0;
#pragma unroll
        for (int i = 0; i < 16; i++) {
            int l = tid + (i << 7);
            float m = Mc[l];
            if (m > v0) { v1 = v0; i1 = i0; v0 = m; i0 = l; }
            else if (m > v1) { v1 = m; i1 = l; }
        }
        for (int it = 0; it < U_; it++) {
            float bvv = v0; int bi = i0;
#pragma unroll
            for (int o = 16; o; o >>= 1) {
                float ov = __shfl_xor_sync(0xffffffffu, bvv, o);
                int   oi = __shfl_xor_sync(0xffffffffu, bi, o);
                if (ov > bvv || (ov == bvv && oi < bi)) { bvv = ov; bi = oi; }
            }
            const int p = it & 1;
            if (lane == 0) { slotV[p * 4 + warp] = bvv; slotI[p * 4 + warp] = bi; }
            __syncthreads();
            float gv = slotV[p * 4 + 0]; int gi = slotI[p * 4 + 0];
#pragma unroll
            for (int w = 1; w < 4; w++) {
                float wv = slotV[p * 4 + w]; int wi = slotI[p * 4 + w];
                if (wv > gv || (wv == gv && wi < gi)) { gv = wv; gi = wi; }
            }
            if (tid == 0) sTop[it] = gi;
            if ((gi & 127) == tid) {
                rm |= 1u << (gi >> 7);
                v0 = v1; i0 = i1; v1 = NEG_INF; i1 = 0;
                if (v0 == NEG_INF) {   // rescan unmasked (rare)
                    for (int i = 0; i < 16; i++) {
                        if (!(rm & (1u << i))) {
                            int l = tid + (i << 7);
                            float m = Mc[l];
                            if (m > v0) { v1 = v0; i1 = i0; v0 = m; i0 = l; }
                            else if (m > v1) { v1 = m; i1 = l; }
                        }
                    }
                }
            }
        }
        __syncthreads();
    }

    // ---- S4: attention rows (10 per warp, chunks of 5, LDS.64 reads) ----
    {
        const float LOG2E = 1.4426950408889634f;
        const float2* xc2 = (const float2*)xc;
#pragma unroll
        for (int ch = 0; ch < 2; ch++) {
            const int ub = warp * 10 + ch * 5;
            float a2[5], m2n[5];
#pragma unroll
            for (int u = 0; u < 5; u++) {
                int t = sTop[ub + u];
                float qt = fmaf(Wq, xc[t], bq);
                float a = qt * Wk;
                a2[u] = a * LOG2E;
                m2n[u] = -(a2[u] * ((a >= 0.f) ? xmx : xmn));
            }
            const float2 a01 = make_float2(a2[0], a2[1]);
            const float2 a23 = make_float2(a2[2], a2[3]);
            const float2 mn01 = make_float2(m2n[0], m2n[1]);
            const float2 mn23 = make_float2(m2n[2], m2n[3]);
            float2 s01 = make_float2(0.f, 0.f), s23 = s01, sv01 = s01, sv23 = s01;
            float s4 = 0.f, sv4 = 0.f;
#pragma unroll 4
            for (int i = 0; i < L_ / 64; i++) {
                float2 xp = xc2[lane + i * 32];
                S4BODY(xp.x)
                S4BODY(xp.y)
            }
            float s[5]  = {s01.x, s01.y, s23.x, s23.y, s4};
            float sv[5] = {sv01.x, sv01.y, sv23.x, sv23.y, sv4};
#pragma unroll
            for (int u = 0; u < 5; u++) {
#pragma unroll
                for (int o = 16; o; o >>= 1) {
                    s[u]  += __shfl_xor_sync(0xffffffffu, s[u], o);
                    sv[u] += __shfl_xor_sync(0xffffffffu, sv[u], o);
                }
                if (lane == 0) sUpd[ub + u] = fmaf(Wv, sv[u] / s[u], bvc);
            }
        }
        __syncthreads();
    }

    // ---- S5: residual + LN -> GELU MLP -> LN (in place over xc) ----
    {
        const float Wo = *pWo, bo = *pbo;
        const float K0 = fmaf(Wo, vmean, bo);

        if (tid < U_) {
            int l = sTop[tid];
            xc[l] += Wo * (sUpd[tid] - vmean);
        }
        __syncthreads();

        float s1 = 0.f, s2 = 0.f;
#pragma unroll
        for (int i = 0; i < 16; i++) {
            int l = tid + (i << 7);
            float z = xc[l] + K0;
            xc[l] = z;
            s1 += z; s2 = fmaf(z, z, s2);
        }
#pragma unroll
        for (int o = 16; o; o >>= 1) {
            s1 += __shfl_xor_sync(0xffffffffu, s1, o);
            s2 += __shfl_xor_sync(0xffffffffu, s2, o);
        }
        if (lane == 0) { sR[warp * 2] = s1; sR[warp * 2 + 1] = s2; }
        __syncthreads();
        s1 = sR[0] + sR[2] + sR[4] + sR[6];
        s2 = sR[1] + sR[3] + sR[5] + sR[7];
        float mean = s1 * invL;
        float rstd = rsqrtf(s2 * invL - mean * mean + 1e-5f);

        const float w1 = *pw1, b1 = *pb1, w2 = *pw2, b2 = *pb2;
        const float g1 = *pg1, be1 = *pbe1;
        float t1 = 0.f, t2 = 0.f;
#pragma unroll 4
        for (int i = 0; i < 16; i++) {
            int l = tid + (i << 7);
            float x1v = fmaf((xc[l] - mean) * rstd, g1, be1);
            float yv  = fmaf(w1, x1v, b1);
            float ge  = 0.5f * yv * (1.0f + erff(yv * 0.70710678118654752f));
            float h   = x1v + fmaf(w2, ge, b2);
            xc[l] = h;
            t1 += h; t2 = fmaf(h, h, t2);
        }
#pragma unroll
        for (int o = 16; o; o >>= 1) {
            t1 += __shfl_xor_sync(0xffffffffu, t1, o);
            t2 += __shfl_xor_sync(0xffffffffu, t2, o);
        }
        if (lane == 0) { sR[8 + warp * 2] = t1; sR[9 + warp * 2] = t2; }
        __syncthreads();
        t1 = sR[8] + sR[10] + sR[12] + sR[14];
        t2 = sR[9] + sR[11] + sR[13] + sR[15];
        float mean2 = t1 * invL;
        float rstd2 = rsqrtf(t2 * invL - mean2 * mean2 + 1e-5f);

        const float g2 = *pg2, be2 = *pbe2;
        float* orow = outT + ((size_t)b * C_ + c) * L_;
#pragma unroll
        for (int i = 0; i < 16; i++) {
            int l = tid + (i << 7);
            orow[l] = fmaf((xc[l] - mean2) * rstd2, g2, be2);
        }
    }
}

extern "C" void kernel_launch(void* const* d_in, const int* in_sizes, int n_in,
                              void* d_out, int out_size) {
    const float* x = (const float*)d_in[0];
    const int* isamp = (const int*)d_in[17];
    float* out = (float*)d_out;

    float *xT = nullptr, *oT = nullptr, *Mp = nullptr;
    int4* iT = nullptr;
    cudaGetSymbolAddress((void**)&xT, g_xT);
    cudaGetSymbolAddress((void**)&oT, g_outT);
    cudaGetSymbolAddress((void**)&Mp, g_Mp);
    cudaGetSymbolAddress((void**)&iT, g_isampT);

    // one-time resources (created on the uncaptured correctness call; no device
    // memory allocation involved)
    static cudaStream_t s1 = nullptr;
    static cudaEvent_t mEv[NCHUNK], jEv;
    if (s1 == nullptr) {
        cudaStreamCreateWithFlags(&s1, cudaStreamNonBlocking);
        for (int k = 0; k < NCHUNK; k++)
            cudaEventCreateWithFlags(&mEv[k], cudaEventDisableTiming);
        cudaEventCreateWithFlags(&jEv, cudaEventDisableTiming);
        cudaFuncSetAttribute(informer_measure,
                             cudaFuncAttributeMaxDynamicSharedMemorySize, 4 * L_ * 4);
        cudaFuncSetAttribute(informer_attn,
                             cudaFuncAttributeMaxDynamicSharedMemorySize, (int)SMEMB_BYTES);
    }

    dim3 tb4(8, 32);
    // stream 0: input transposes, then measure chunks
    transpose4_k<<<dim3(C_ / 32, L_ / 32, B_), tb4>>>(xT, x, L_, C_);
    transpose_idx<<<L_ / 256, 256>>>(iT, isamp);

    for (int k = 0; k < NCHUNK; k++) {
        informer_measure<<<dim3(CCHUNK, B_ / GJ), NTHA, 4 * L_ * 4>>>(
            xT, Mp, iT, k * CCHUNK,
            (const float*)d_in[1], (const float*)d_in[2],
            (const float*)d_in[3], (const float*)d_in[4]);
        cudaEventRecord(mEv[k], 0);
    }

    // side stream: attn chunk k waits only on measure chunk k
    for (int k = 0; k < NCHUNK; k++) {
        cudaStreamWaitEvent(s1, mEv[k], 0);
        informer_attn<<<dim3(CCHUNK, B_), NTHB, SMEMB_BYTES, s1>>>(
            xT, oT, Mp, k * CCHUNK,
            (const float*)d_in[1],  (const float*)d_in[2],  (const float*)d_in[3],  (const float*)d_in[4],
            (const float*)d_in[5],  (const float*)d_in[6],  (const float*)d_in[7],  (const float*)d_in[8],
            (const float*)d_in[9],  (const float*)d_in[10], (const float*)d_in[11], (const float*)d_in[12],
            (const float*)d_in[13], (const float*)d_in[14], (const float*)d_in[15], (const float*)d_in[16]);
    }
    cudaEventRecord(jEv, s1);
    cudaStreamWaitEvent(0, jEv, 0);

    // output transpose after all attn chunks
    transpose4_k<<<dim3(L_ / 32, C_ / 32, B_), tb4>>>(out, oT, C_, L_);
}

// round 13
// speedup vs baseline: 1.3165x; 1.3165x over previous
#include <cuda_runtime.h>
#include <cstdint>
#include <cstddef>

#define B_  16
#define L_  2048
#define C_  128
#define U_  40
#define GJ  4
#define NTH 512

#define NEG_INF __int_as_float(0xff800000)
#define POS_INF __int_as_float(0x7f800000)

// scratch (device globals: no allocation allowed)
__device__ float g_xT[B_ * C_ * L_];
__device__ float g_outT[B_ * C_ * L_];
__device__ int4  g_isampT[(U_ / 4) * L_];   // [q][l]

// ---------------------------------------------------------------------------
// float4 batched transpose: src (NI, NJ) -> dst (NJ, NI), per batch z.
__global__ void transpose4_k(float* __restrict__ dst, const float* __restrict__ src,
                             int NI, int NJ) {
    __shared__ float tile[32][33];
    const int z = blockIdx.z;
    const float* s = src + (size_t)z * NI * NJ;
    float* d = dst + (size_t)z * NI * NJ;
    const int j0 = blockIdx.x * 32, i0 = blockIdx.y * 32;
    const int tx = threadIdx.x, ty = threadIdx.y;
    float4 v = *(const float4*)&s[(size_t)(i0 + ty) * NJ + j0 + tx * 4];
    tile[ty][tx * 4 + 0] = v.x;
    tile[ty][tx * 4 + 1] = v.y;
    tile[ty][tx * 4 + 2] = v.z;
    tile[ty][tx * 4 + 3] = v.w;
    __syncthreads();
    float4 o;
    o.x = tile[tx * 4 + 0][ty];
    o.y = tile[tx * 4 + 1][ty];
    o.z = tile[tx * 4 + 2][ty];
    o.w = tile[tx * 4 + 3][ty];
    *(float4*)&d[(size_t)(j0 + ty) * NI + i0 + tx * 4] = o;
}

// isamp (L x U ints) -> isampT[q][l] (10 x 2048 int4)
__global__ void transpose_idx(int4* __restrict__ dst, const int* __restrict__ src) {
    __shared__ int4 st[256 * (U_ / 4)];
    const int lb = blockIdx.x * 256;
    const int4* s = (const int4*)(src + (size_t)lb * U_);
    for (int i = threadIdx.x; i < 256 * (U_ / 4); i += 256) st[i] = s[i];
    __syncthreads();
#pragma unroll
    for (int q = 0; q < U_ / 4; q++)
        dst[q * L_ + lb + threadIdx.x] = st[threadIdx.x * (U_ / 4) + q];
}

__global__ void dummy_k() {}

__device__ __forceinline__ float fexp2(float x) {
    float y;
    asm("ex2.approx.ftz.f32 %0, %1;" : "=f"(y) : "f"(x));
    return y;
}

// packed fp16x2 exp2: one MUFU op for two exps (args <= 0, result in [0,1])
__device__ __forceinline__ float2 exp2_pair(float2 p) {
    unsigned h;
    asm("{\n\t.reg .b32 t;\n\t"
        "cvt.rn.f16x2.f32 t, %2, %1;\n\t"   // upper = p.y, lower = p.x
        "ex2.approx.f16x2 t, t;\n\t"
        "mov.b32 %0, t;\n\t}"
        : "=r"(h) : "f"(p.x), "f"(p.y));
    float2 r;
    asm("{\n\t.reg .b16 lo, hi;\n\t"
        "mov.b32 {lo, hi}, %2;\n\t"
        "cvt.f32.f16 %0, lo;\n\t"
        "cvt.f32.f16 %1, hi;\n\t}"
        : "=f"(r.x), "=f"(r.y) : "r"(h));
    return r;
}

// ---- Blackwell packed f32x2 ops ---------------------------------------------
__device__ __forceinline__ float2 f2mul(float2 a, float2 b) {
    float2 r;
    asm("{\n\t.reg .b64 ra, rb, rc;\n\t"
        "mov.b64 ra, {%2, %3};\n\t"
        "mov.b64 rb, {%4, %5};\n\t"
        "mul.rn.f32x2 rc, ra, rb;\n\t"
        "mov.b64 {%0, %1}, rc;\n\t}"
        : "=f"(r.x), "=f"(r.y) : "f"(a.x), "f"(a.y), "f"(b.x), "f"(b.y));
    return r;
}
__device__ __forceinline__ float2 f2add(float2 a, float2 b) {
    float2 r;
    asm("{\n\t.reg .b64 ra, rb, rc;\n\t"
        "mov.b64 ra, {%2, %3};\n\t"
        "mov.b64 rb, {%4, %5};\n\t"
        "add.rn.f32x2 rc, ra, rb;\n\t"
        "mov.b64 {%0, %1}, rc;\n\t}"
        : "=f"(r.x), "=f"(r.y) : "f"(a.x), "f"(a.y), "f"(b.x), "f"(b.y));
    return r;
}
__device__ __forceinline__ float2 f2fma(float2 a, float2 b, float2 c) {
    float2 r;
    asm("{\n\t.reg .b64 ra, rb, rc, rd;\n\t"
        "mov.b64 ra, {%2, %3};\n\t"
        "mov.b64 rb, {%4, %5};\n\t"
        "mov.b64 rc, {%6, %7};\n\t"
        "fma.rn.f32x2 rd, ra, rb, rc;\n\t"
        "mov.b64 {%0, %1}, rd;\n\t}"
        : "=f"(r.x), "=f"(r.y)
        : "f"(a.x), "f"(a.y), "f"(b.x), "f"(b.y), "f"(c.x), "f"(c.y));
    return r;
}

__device__ __forceinline__ void group_bar(int j) {
    asm volatile("bar.sync %0, 128;" :: "r"(j + 1) : "memory");
}

// shared layout (floats)
static constexpr int SM_XS4   = 0;                    // 4L: float4 xs4[l]
static constexpr int SM_MSM   = SM_XS4 + 4 * L_;      // 4L: M[j*L+l]; later xc[j*L+l]
static constexpr int SM_XMAX  = SM_MSM + GJ * L_;
static constexpr int SM_XMIN  = SM_XMAX + 4;
static constexpr int SM_VMEAN = SM_XMIN + 4;
static constexpr int SM_XSUM  = SM_VMEAN + 4;
static constexpr int SM_XSQ   = SM_XSUM + 4;
static constexpr int SM_UPD   = SM_XSQ + 4;
static constexpr int SM_TOP   = SM_UPD + GJ * U_;
static constexpr int SM_STAGE = SM_TOP + GJ * U_;     // 256 (16 warps x 4 batches x 4)
static constexpr int SM_SLOTV = SM_STAGE + 256;       // 32
static constexpr int SM_SLOTI = SM_SLOTV + 32;        // 32
static constexpr int SM_R5    = SM_SLOTI + 32;        // 64
static constexpr int SM_CONST = SM_R5 + 64;           // 16
static constexpr int SM_FLOATS_TOTAL = SM_CONST + 16;
static constexpr size_t SMEM_BYTES = (size_t)SM_FLOATS_TOTAL * 4;

#define GATH4(ii)                                                     \
    {                                                                 \
        float4 g = xs4[ii];                                           \
        float2 t01 = f2mul(A01, make_float2(g.x, g.y));               \
        float2 t23 = f2mul(A23, make_float2(g.z, g.w));               \
        gm0 = fmaxf(gm0, t01.x); gm1 = fmaxf(gm1, t01.y);             \
        gm2 = fmaxf(gm2, t23.x); gm3 = fmaxf(gm3, t23.y);             \
        gs01 = f2add(gs01, make_float2(g.x, g.y));                    \
        gs23 = f2add(gs23, make_float2(g.z, g.w));                    \
    }

// inner S4 body for one x value (paired exps through f16x2 MUFU)
#define S4BODY(xv)                                                    \
    {                                                                 \
        float2 xv2 = make_float2((xv), (xv));                         \
        float2 p01 = f2fma(a01, xv2, mn01);                           \
        float2 p23 = f2fma(a23, xv2, mn23);                           \
        float p4 = fmaf(a2[4], (xv), m2n[4]);                         \
        float2 e01 = exp2_pair(p01);                                  \
        float2 e23 = exp2_pair(p23);                                  \
        float e4 = fexp2(p4);                                         \
        s01 = f2add(s01, e01);                                        \
        s23 = f2add(s23, e23);                                        \
        s4 += e4;                                                     \
        sv01 = f2fma(e01, xv2, sv01);                                 \
        sv23 = f2fma(e23, xv2, sv23);                                 \
        sv4 = fmaf(e4, (xv), sv4);                                    \
    }

__global__ void __launch_bounds__(NTH, 3)
informer_main(const float* __restrict__ xT, float* __restrict__ outT,
              const int4* __restrict__ isampT,
              const float* pWq, const float* pbq, const float* pWk, const float* pbk,
              const float* pWv, const float* pbv, const float* pWo, const float* pbo,
              const float* pw1, const float* pb1, const float* pw2, const float* pb2,
              const float* pg1, const float* pbe1, const float* pg2, const float* pbe2) {
    const int c    = blockIdx.x;
    const int b0   = blockIdx.y * GJ;
    const int tid  = threadIdx.x;
    const int lane = tid & 31, warp = tid >> 5;
    const int j    = warp >> 2;        // batch group (128 threads each)
    const int t128 = tid & 127;
    const int wig  = warp & 3;

    extern __shared__ float sm[];
    float4* xs4  = (float4*)(sm + SM_XS4);
    float*  xsf  = sm + SM_XS4;
    float*  Msm  = sm + SM_MSM;
    float* sXmax = sm + SM_XMAX;
    float* sXmin = sm + SM_XMIN;
    float* sVmean= sm + SM_VMEAN;
    float* sXsum = sm + SM_XSUM;
    float* sXsq  = sm + SM_XSQ;
    float* sUpd  = sm + SM_UPD;
    int*   sTop  = (int*)(sm + SM_TOP);
    float* sStg  = sm + SM_STAGE;
    float* slotV = sm + SM_SLOTV;
    int*   slotI = (int*)(sm + SM_SLOTI);
    float* sR5   = sm + SM_R5;
    float* sC    = sm + SM_CONST;

    if (tid == 0) {
        sC[0]=*pWq; sC[1]=*pbq; sC[2]=*pWk;  sC[3]=*pbk;
        sC[4]=*pWv; sC[5]=*pbv; sC[6]=*pWo;  sC[7]=*pbo;
        sC[8]=*pw1; sC[9]=*pb1; sC[10]=*pw2; sC[11]=*pb2;
        sC[12]=*pg1; sC[13]=*pbe1; sC[14]=*pg2; sC[15]=*pbe2;
    }
    const float invL = 1.0f / (float)L_;

    // ---------------- S1: load columns -> float4 interleaved, stats ---------
    {
        float v[GJ][L_ / NTH];
        float lmax[GJ], lmin[GJ], lsum[GJ], lsq[GJ];
#pragma unroll
        for (int jj = 0; jj < GJ; jj++) {
            lmax[jj] = NEG_INF; lmin[jj] = POS_INF; lsum[jj] = 0.f; lsq[jj] = 0.f;
            const float* row = xT + ((size_t)(b0 + jj) * C_ + c) * L_;
#pragma unroll
            for (int i = 0; i < L_ / NTH; i++) {
                float x = row[tid + i * NTH];
                v[jj][i] = x;
                lmax[jj] = fmaxf(lmax[jj], x);
                lmin[jj] = fminf(lmin[jj], x);
                lsum[jj] += x;
                lsq[jj] = fmaf(x, x, lsq[jj]);
            }
        }
#pragma unroll
        for (int i = 0; i < L_ / NTH; i++)
            xs4[tid + i * NTH] = make_float4(v[0][i], v[1][i], v[2][i], v[3][i]);
#pragma unroll
        for (int jj = 0; jj < GJ; jj++) {
#pragma unroll
            for (int o = 16; o; o >>= 1) {
                lmax[jj] = fmaxf(lmax[jj], __shfl_xor_sync(0xffffffffu, lmax[jj], o));
                lmin[jj] = fminf(lmin[jj], __shfl_xor_sync(0xffffffffu, lmin[jj], o));
                lsum[jj] += __shfl_xor_sync(0xffffffffu, lsum[jj], o);
                lsq[jj]  += __shfl_xor_sync(0xffffffffu, lsq[jj], o);
            }
        }
        if (lane == 0) {
#pragma unroll
            for (int jj = 0; jj < GJ; jj++) {
                sStg[(warp * GJ + jj) * 4 + 0] = lmax[jj];
                sStg[(warp * GJ + jj) * 4 + 1] = lmin[jj];
                sStg[(warp * GJ + jj) * 4 + 2] = lsum[jj];
                sStg[(warp * GJ + jj) * 4 + 3] = lsq[jj];
            }
        }
        __syncthreads();
        if (tid < GJ) {
            float mx = NEG_INF, mn = POS_INF, s = 0.f, s2 = 0.f;
            for (int w = 0; w < NTH / 32; w++) {
                mx = fmaxf(mx, sStg[(w * GJ + tid) * 4 + 0]);
                mn = fminf(mn, sStg[(w * GJ + tid) * 4 + 1]);
                s += sStg[(w * GJ + tid) * 4 + 2];
                s2 += sStg[(w * GJ + tid) * 4 + 3];
            }
            sXmax[tid]  = mx;
            sXmin[tid]  = mn;
            sXsum[tid]  = s;
            sXsq[tid]   = s2;
            sVmean[tid] = fmaf(sC[4], s * invL, sC[5]);
        }
        __syncthreads();
    }

    // ---------------- S2: sparsity measure M (sign-folded, f32x2) -----------
    {
        const float Wq = sC[0], bq = sC[1], Wk = sC[2], bk = sC[3];
#pragma unroll
        for (int i = 0; i < L_ / NTH; i++) {
            int l = tid + i * NTH;
            float4 xc = xs4[l];
            const float q0 = fmaf(Wq, xc.x, bq), q1 = fmaf(Wq, xc.y, bq);
            const float q2 = fmaf(Wq, xc.z, bq), q3 = fmaf(Wq, xc.w, bq);
            const float2 A01 = make_float2(q0 * Wk, q1 * Wk);
            const float2 A23 = make_float2(q2 * Wk, q3 * Wk);
            const float B00 = q0 * bk, B01 = q1 * bk, B02 = q2 * bk, B03 = q3 * bk;

            float gm0 = NEG_INF, gm1 = NEG_INF, gm2 = NEG_INF, gm3 = NEG_INF;
            float2 gs01 = make_float2(0.f, 0.f), gs23 = make_float2(0.f, 0.f);
#pragma unroll
            for (int q = 0; q < U_ / 4; q++) {
                int4 iv = __ldg(&isampT[q * L_ + l]);
                GATH4(iv.x) GATH4(iv.y) GATH4(iv.z) GATH4(iv.w)
            }
            Msm[0 * L_ + l] = (gm0 + B00) - fmaf(A01.x, gs01.x, (float)U_ * B00) * invL;
            Msm[1 * L_ + l] = (gm1 + B01) - fmaf(A01.y, gs01.y, (float)U_ * B01) * invL;
            Msm[2 * L_ + l] = (gm2 + B02) - fmaf(A23.x, gs23.x, (float)U_ * B02) * invL;
            Msm[3 * L_ + l] = (gm3 + B03) - fmaf(A23.y, gs23.y, (float)U_ * B03) * invL;
        }
    }
    __syncthreads();

    // From here on: 128-thread groups (batch j) are independent.

    // ---------------- S3: top-U, stripe top-2 cache + removal mask ----------
    {
        const float* Mj = Msm + j * L_;
        float v0 = NEG_INF, v1 = NEG_INF;
        int i0 = 0, i1 = 0;
        unsigned rm = 0;
#pragma unroll
        for (int i = 0; i < 16; i++) {
            int l = t128 + (i << 7);
            float m = Mj[l];
            if (m > v0) { v1 = v0; i1 = i0; v0 = m; i0 = l; }
            else if (m > v1) { v1 = m; i1 = l; }
        }
        for (int it = 0; it < U_; it++) {
            float bvv = v0; int bi = i0;
#pragma unroll
            for (int o = 16; o; o >>= 1) {
                float ov = __shfl_xor_sync(0xffffffffu, bvv, o);
                int   oi = __shfl_xor_sync(0xffffffffu, bi, o);
                if (ov > bvv || (ov == bvv && oi < bi)) { bvv = ov; bi = oi; }
            }
            const int p = it & 1;
            const int sb = (j * 2 + p) * 4;
            if (lane == 0) { slotV[sb + wig] = bvv; slotI[sb + wig] = bi; }
            group_bar(j);
            float gv = slotV[sb + 0]; int gi = slotI[sb + 0];
#pragma unroll
            for (int w = 1; w < 4; w++) {
                float wv = slotV[sb + w]; int wi = slotI[sb + w];
                if (wv > gv || (wv == gv && wi < gi)) { gv = wv; gi = wi; }
            }
            if (t128 == 0) sTop[j * U_ + it] = gi;
            if ((gi & 127) == t128) {
                rm |= 1u << (gi >> 7);
                v0 = v1; i0 = i1; v1 = NEG_INF; i1 = 0;
                if (v0 == NEG_INF) {   // cache exhausted: rescan unmasked
                    for (int i = 0; i < 16; i++) {
                        if (!(rm & (1u << i))) {
                            int l = t128 + (i << 7);
                            float m = Mj[l];
                            if (m > v0) { v1 = v0; i1 = i0; v0 = m; i0 = l; }
                            else if (m > v1) { v1 = m; i1 = l; }
                        }
                    }
                }
            }
        }
        group_bar(j);
    }

    // ---------------- S3b: re-materialize contiguous batch column -----------
    float* xcj = Msm + j * L_;
    {
#pragma unroll
        for (int i = 0; i < 16; i++) {
            int l = t128 + (i << 7);
            xcj[l] = xsf[l * 4 + j];
        }
        group_bar(j);
    }

    // ---------------- S4: attention rows (f16x2 exps, LDS.64 reads) ---------
    {
        const float Wq = sC[0], bq = sC[1], Wk = sC[2];
        const float Wv = sC[4], bvc = sC[5];
        const float xmx = sXmax[j], xmn = sXmin[j];
        const float LOG2E = 1.4426950408889634f;
        const float2* xc2 = (const float2*)xcj;
#pragma unroll
        for (int ch = 0; ch < 2; ch++) {
            const int ub = wig * 10 + ch * 5;
            float a2[5], m2n[5];
#pragma unroll
            for (int u = 0; u < 5; u++) {
                int t = sTop[j * U_ + ub + u];
                float qt = fmaf(Wq, xcj[t], bq);
                float a = qt * Wk;
                a2[u] = a * LOG2E;
                m2n[u] = -(a2[u] * ((a >= 0.f) ? xmx : xmn));
            }
            const float2 a01 = make_float2(a2[0], a2[1]);
            const float2 a23 = make_float2(a2[2], a2[3]);
            const float2 mn01 = make_float2(m2n[0], m2n[1]);
            const float2 mn23 = make_float2(m2n[2], m2n[3]);
            float2 s01 = make_float2(0.f, 0.f), s23 = s01, sv01 = s01, sv23 = s01;
            float s4 = 0.f, sv4 = 0.f;
#pragma unroll 4
            for (int i = 0; i < L_ / 64; i++) {
                float2 xp = xc2[lane + i * 32];   // LDS.64, conflict-free
                S4BODY(xp.x)
                S4BODY(xp.y)
            }
            float s[5]  = {s01.x, s01.y, s23.x, s23.y, s4};
            float sv[5] = {sv01.x, sv01.y, sv23.x, sv23.y, sv4};
#pragma unroll
            for (int u = 0; u < 5; u++) {
#pragma unroll
                for (int o = 16; o; o >>= 1) {
                    s[u]  += __shfl_xor_sync(0xffffffffu, s[u], o);
                    sv[u] += __shfl_xor_sync(0xffffffffu, sv[u], o);
                }
                if (lane == 0) sUpd[j * U_ + ub + u] = fmaf(Wv, sv[u] / s[u], bvc);
            }
        }
        group_bar(j);
    }

    // ---------------- S5: fixups + analytic LN1 -> GELU MLP -> LN2 ----------
    {
        const float Wo = sC[6], bo = sC[7];
        const float vm = sVmean[j];
        const float K0 = fmaf(Wo, vm, bo);

        // fixups at top indices; accumulate correction sums D1, D2
        float d1 = 0.f, d2 = 0.f;
        if (t128 < U_) {
            int l = sTop[j * U_ + t128];
            float xold = xcj[l];
            float d = Wo * (sUpd[j * U_ + t128] - vm);
            xcj[l] = xold + d;
            d1 = d;
            d2 = d * (2.f * (xold + K0) + d);
        }
#pragma unroll
        for (int o = 16; o; o >>= 1) {
            d1 += __shfl_xor_sync(0xffffffffu, d1, o);
            d2 += __shfl_xor_sync(0xffffffffu, d2, o);
        }
        if (lane == 0) { sR5[j * 16 + wig * 2] = d1; sR5[j * 16 + wig * 2 + 1] = d2; }
        group_bar(j);
        const float D1 = sR5[j * 16 + 0] + sR5[j * 16 + 2] + sR5[j * 16 + 4] + sR5[j * 16 + 6];
        const float D2 = sR5[j * 16 + 1] + sR5[j * 16 + 3] + sR5[j * 16 + 5] + sR5[j * 16 + 7];

        // analytic LN1 stats: z = x + K0 (+ fixups)
        const float Sx  = sXsum[j];
        const float Sx2 = sXsq[j];
        const float mean = (Sx + (float)L_ * K0 + D1) * invL;
        const float Szz  = Sx2 + 2.f * K0 * Sx + (float)L_ * K0 * K0 + D2;
        const float rstd = rsqrtf(Szz * invL - mean * mean + 1e-5f);
        const float meanAdj = mean - K0;   // z - mean == xcj - meanAdj

        const float w1 = sC[8], b1 = sC[9], w2 = sC[10], b2 = sC[11];
        const float g1 = sC[12], be1 = sC[13];
        float t1 = 0.f, t2 = 0.f;
#pragma unroll 4
        for (int i = 0; i < 16; i++) {
            int l = t128 + (i << 7);
            float x1v = fmaf((xcj[l] - meanAdj) * rstd, g1, be1);
            float yv  = fmaf(w1, x1v, b1);
            float ge  = 0.5f * yv * (1.0f + erff(yv * 0.70710678118654752f));
            float h   = x1v + fmaf(w2, ge, b2);
            xcj[l] = h;
            t1 += h; t2 = fmaf(h, h, t2);
        }
#pragma unroll
        for (int o = 16; o; o >>= 1) {
            t1 += __shfl_xor_sync(0xffffffffu, t1, o);
            t2 += __shfl_xor_sync(0xffffffffu, t2, o);
        }
        if (lane == 0) { sR5[j * 16 + 8 + wig * 2] = t1; sR5[j * 16 + 9 + wig * 2] = t2; }
        group_bar(j);
        t1 = sR5[j * 16 + 8]  + sR5[j * 16 + 10] + sR5[j * 16 + 12] + sR5[j * 16 + 14];
        t2 = sR5[j * 16 + 9]  + sR5[j * 16 + 11] + sR5[j * 16 + 13] + sR5[j * 16 + 15];
        float mean2 = t1 * invL;
        float rstd2 = rsqrtf(t2 * invL - mean2 * mean2 + 1e-5f);

        const float g2 = sC[14], be2 = sC[15];
        float* orow = outT + ((size_t)(b0 + j) * C_ + c) * L_;
#pragma unroll
        for (int i = 0; i < 16; i++) {
            int l = t128 + (i << 7);
            orow[l] = fmaf((xcj[l] - mean2) * rstd2, g2, be2);
        }
    }
}

extern "C" void kernel_launch(void* const* d_in, const int* in_sizes, int n_in,
                              void* d_out, int out_size) {
    const float* x = (const float*)d_in[0];
    const int* isamp = (const int*)d_in[17];
    float* out = (float*)d_out;

    float *xT = nullptr, *oT = nullptr;
    int4* iT = nullptr;
    cudaGetSymbolAddress((void**)&xT, g_xT);
    cudaGetSymbolAddress((void**)&oT, g_outT);
    cudaGetSymbolAddress((void**)&iT, g_isampT);

    cudaFuncSetAttribute(informer_main, cudaFuncAttributeMaxDynamicSharedMemorySize,
                         (int)SMEM_BYTES);

    dim3 tb4(8, 32);
    // main at launch index 3 (ncu skip=3 lands on it)
    transpose4_k<<<dim3(C_ / 32, L_ / 32, B_), tb4>>>(xT, x, L_, C_); // 0
    transpose_idx<<<L_ / 256, 256>>>(iT, isamp);                      // 1
    dummy_k<<<1, 32>>>();                                             // 2

    informer_main<<<dim3(C_, B_ / GJ), NTH, SMEM_BYTES>>>(            // 3
        xT, oT, iT,
        (const float*)d_in[1],  (const float*)d_in[2],  (const float*)d_in[3],  (const float*)d_in[4],
        (const float*)d_in[5],  (const float*)d_in[6],  (const float*)d_in[7],  (const float*)d_in[8],
        (const float*)d_in[9],  (const float*)d_in[10], (const float*)d_in[11], (const float*)d_in[12],
        (const float*)d_in[13], (const float*)d_in[14], (const float*)d_in[15], (const float*)d_in[16]);

    transpose4_k<<<dim3(L_ / 32, C_ / 32, B_), tb4>>>(out, oT, C_, L_); // 4
}

// round 14
// speedup vs baseline: 1.3395x; 1.0175x over previous
#include <cuda_runtime.h>
#include <cstdint>
#include <cstddef>

#define B_  16
#define L_  2048
#define C_  128
#define U_  40
#define GJ  4
#define NTH 512

#define NEG_INF __int_as_float(0xff800000)
#define POS_INF __int_as_float(0x7f800000)

// scratch (device globals: no allocation allowed)
__device__ float g_xT[B_ * C_ * L_];
__device__ float g_outT[B_ * C_ * L_];
__device__ int4  g_isampT[(U_ / 4) * L_];   // [q][l]

// ---------------------------------------------------------------------------
// float4 batched transpose: src (NI, NJ) -> dst (NJ, NI), per batch z.
__global__ void transpose4_k(float* __restrict__ dst, const float* __restrict__ src,
                             int NI, int NJ) {
    __shared__ float tile[32][33];
    const int z = blockIdx.z;
    const float* s = src + (size_t)z * NI * NJ;
    float* d = dst + (size_t)z * NI * NJ;
    const int j0 = blockIdx.x * 32, i0 = blockIdx.y * 32;
    const int tx = threadIdx.x, ty = threadIdx.y;
    float4 v = *(const float4*)&s[(size_t)(i0 + ty) * NJ + j0 + tx * 4];
    tile[ty][tx * 4 + 0] = v.x;
    tile[ty][tx * 4 + 1] = v.y;
    tile[ty][tx * 4 + 2] = v.z;
    tile[ty][tx * 4 + 3] = v.w;
    __syncthreads();
    float4 o;
    o.x = tile[tx * 4 + 0][ty];
    o.y = tile[tx * 4 + 1][ty];
    o.z = tile[tx * 4 + 2][ty];
    o.w = tile[tx * 4 + 3][ty];
    *(float4*)&d[(size_t)(j0 + ty) * NI + i0 + tx * 4] = o;
}

// isamp (L x U ints) -> isampT[q][l] (10 x 2048 int4)
__global__ void transpose_idx(int4* __restrict__ dst, const int* __restrict__ src) {
    __shared__ int4 st[256 * (U_ / 4)];
    const int lb = blockIdx.x * 256;
    const int4* s = (const int4*)(src + (size_t)lb * U_);
    for (int i = threadIdx.x; i < 256 * (U_ / 4); i += 256) st[i] = s[i];
    __syncthreads();
#pragma unroll
    for (int q = 0; q < U_ / 4; q++)
        dst[q * L_ + lb + threadIdx.x] = st[threadIdx.x * (U_ / 4) + q];
}

__global__ void dummy_k() {}

__device__ __forceinline__ float fexp2(float x) {
    float y;
    asm("ex2.approx.ftz.f32 %0, %1;" : "=f"(y) : "f"(x));
    return y;
}

// ---- Blackwell packed f32x2 ops ---------------------------------------------
__device__ __forceinline__ float2 f2mul(float2 a, float2 b) {
    float2 r;
    asm("{\n\t.reg .b64 ra, rb, rc;\n\t"
        "mov.b64 ra, {%2, %3};\n\t"
        "mov.b64 rb, {%4, %5};\n\t"
        "mul.rn.f32x2 rc, ra, rb;\n\t"
        "mov.b64 {%0, %1}, rc;\n\t}"
        : "=f"(r.x), "=f"(r.y) : "f"(a.x), "f"(a.y), "f"(b.x), "f"(b.y));
    return r;
}
__device__ __forceinline__ float2 f2add(float2 a, float2 b) {
    float2 r;
    asm("{\n\t.reg .b64 ra, rb, rc;\n\t"
        "mov.b64 ra, {%2, %3};\n\t"
        "mov.b64 rb, {%4, %5};\n\t"
        "add.rn.f32x2 rc, ra, rb;\n\t"
        "mov.b64 {%0, %1}, rc;\n\t}"
        : "=f"(r.x), "=f"(r.y) : "f"(a.x), "f"(a.y), "f"(b.x), "f"(b.y));
    return r;
}
__device__ __forceinline__ float2 f2fma(float2 a, float2 b, float2 c) {
    float2 r;
    asm("{\n\t.reg .b64 ra, rb, rc, rd;\n\t"
        "mov.b64 ra, {%2, %3};\n\t"
        "mov.b64 rb, {%4, %5};\n\t"
        "mov.b64 rc, {%6, %7};\n\t"
        "fma.rn.f32x2 rd, ra, rb, rc;\n\t"
        "mov.b64 {%0, %1}, rd;\n\t}"
        : "=f"(r.x), "=f"(r.y)
        : "f"(a.x), "f"(a.y), "f"(b.x), "f"(b.y), "f"(c.x), "f"(c.y));
    return r;
}

__device__ __forceinline__ void group_bar(int j) {
    asm volatile("bar.sync %0, 128;" :: "r"(j + 1) : "memory");
}

// shared layout (floats)
static constexpr int SM_XS4   = 0;                    // 4L: float4 xs4[l]
static constexpr int SM_MSM   = SM_XS4 + 4 * L_;      // 4L: M[j*L+l]; later xc[j*L+l]
static constexpr int SM_XMAX  = SM_MSM + GJ * L_;
static constexpr int SM_XMIN  = SM_XMAX + 4;
static constexpr int SM_VMEAN = SM_XMIN + 4;
static constexpr int SM_XSUM  = SM_VMEAN + 4;
static constexpr int SM_XSQ   = SM_XSUM + 4;
static constexpr int SM_UPD   = SM_XSQ + 4;
static constexpr int SM_TOP   = SM_UPD + GJ * U_;
static constexpr int SM_STAGE = SM_TOP + GJ * U_;     // 256
static constexpr int SM_SLOTV = SM_STAGE + 256;       // 32
static constexpr int SM_SLOTI = SM_SLOTV + 32;        // 32
static constexpr int SM_R5    = SM_SLOTI + 32;        // 64
static constexpr int SM_CONST = SM_R5 + 64;           // 16
static constexpr int SM_FLOATS_TOTAL = SM_CONST + 16;
static constexpr size_t SMEM_BYTES = (size_t)SM_FLOATS_TOTAL * 4;

#define GATH4(ii)                                                     \
    {                                                                 \
        float4 g = xs4[ii];                                           \
        float2 t01 = f2mul(A01, make_float2(g.x, g.y));               \
        float2 t23 = f2mul(A23, make_float2(g.z, g.w));               \
        gm0 = fmaxf(gm0, t01.x); gm1 = fmaxf(gm1, t01.y);             \
        gm2 = fmaxf(gm2, t23.x); gm3 = fmaxf(gm3, t23.y);             \
        gs01 = f2add(gs01, make_float2(g.x, g.y));                    \
        gs23 = f2add(gs23, make_float2(g.z, g.w));                    \
    }

// inner S4 body for one x value (fp32 MUFU exps)
#define S4BODY(xv)                                                    \
    {                                                                 \
        float2 xv2 = make_float2((xv), (xv));                         \
        float2 p01 = f2fma(a01, xv2, mn01);                           \
        float2 p23 = f2fma(a23, xv2, mn23);                           \
        float p4 = fmaf(a2[4], (xv), m2n[4]);                         \
        float2 e01 = make_float2(fexp2(p01.x), fexp2(p01.y));         \
        float2 e23 = make_float2(fexp2(p23.x), fexp2(p23.y));         \
        float e4 = fexp2(p4);                                         \
        s01 = f2add(s01, e01);                                        \
        s23 = f2add(s23, e23);                                        \
        s4 += e4;                                                     \
        sv01 = f2fma(e01, xv2, sv01);                                 \
        sv23 = f2fma(e23, xv2, sv23);                                 \
        sv4 = fmaf(e4, (xv), sv4);                                    \
    }

__global__ void __launch_bounds__(NTH, 3)
informer_main(const float* __restrict__ xT, float* __restrict__ outT,
              const int4* __restrict__ isampT,
              const float* pWq, const float* pbq, const float* pWk, const float* pbk,
              const float* pWv, const float* pbv, const float* pWo, const float* pbo,
              const float* pw1, const float* pb1, const float* pw2, const float* pb2,
              const float* pg1, const float* pbe1, const float* pg2, const float* pbe2) {
    const int c    = blockIdx.x;
    const int b0   = blockIdx.y * GJ;
    const int tid  = threadIdx.x;
    const int lane = tid & 31, warp = tid >> 5;
    const int j    = warp >> 2;        // batch group (128 threads each)
    const int t128 = tid & 127;
    const int wig  = warp & 3;

    extern __shared__ float sm[];
    float4* xs4  = (float4*)(sm + SM_XS4);
    float*  xsf  = sm + SM_XS4;
    float*  Msm  = sm + SM_MSM;
    float* sXmax = sm + SM_XMAX;
    float* sXmin = sm + SM_XMIN;
    float* sVmean= sm + SM_VMEAN;
    float* sXsum = sm + SM_XSUM;
    float* sXsq  = sm + SM_XSQ;
    float* sUpd  = sm + SM_UPD;
    int*   sTop  = (int*)(sm + SM_TOP);
    float* sStg  = sm + SM_STAGE;
    float* slotV = sm + SM_SLOTV;
    int*   slotI = (int*)(sm + SM_SLOTI);
    float* sR5   = sm + SM_R5;
    float* sC    = sm + SM_CONST;

    if (tid == 0) {
        sC[0]=*pWq; sC[1]=*pbq; sC[2]=*pWk;  sC[3]=*pbk;
        sC[4]=*pWv; sC[5]=*pbv; sC[6]=*pWo;  sC[7]=*pbo;
        sC[8]=*pw1; sC[9]=*pb1; sC[10]=*pw2; sC[11]=*pb2;
        sC[12]=*pg1; sC[13]=*pbe1; sC[14]=*pg2; sC[15]=*pbe2;
    }
    const float invL = 1.0f / (float)L_;

    // ---------------- S1: load columns -> float4 interleaved, stats ---------
    {
        float v[GJ][L_ / NTH];
        float lmax[GJ], lmin[GJ], lsum[GJ], lsq[GJ];
#pragma unroll
        for (int jj = 0; jj < GJ; jj++) {
            lmax[jj] = NEG_INF; lmin[jj] = POS_INF; lsum[jj] = 0.f; lsq[jj] = 0.f;
            const float* row = xT + ((size_t)(b0 + jj) * C_ + c) * L_;
#pragma unroll
            for (int i = 0; i < L_ / NTH; i++) {
                float x = row[tid + i * NTH];
                v[jj][i] = x;
                lmax[jj] = fmaxf(lmax[jj], x);
                lmin[jj] = fminf(lmin[jj], x);
                lsum[jj] += x;
                lsq[jj] = fmaf(x, x, lsq[jj]);
            }
        }
#pragma unroll
        for (int i = 0; i < L_ / NTH; i++)
            xs4[tid + i * NTH] = make_float4(v[0][i], v[1][i], v[2][i], v[3][i]);
#pragma unroll
        for (int jj = 0; jj < GJ; jj++) {
#pragma unroll
            for (int o = 16; o; o >>= 1) {
                lmax[jj] = fmaxf(lmax[jj], __shfl_xor_sync(0xffffffffu, lmax[jj], o));
                lmin[jj] = fminf(lmin[jj], __shfl_xor_sync(0xffffffffu, lmin[jj], o));
                lsum[jj] += __shfl_xor_sync(0xffffffffu, lsum[jj], o);
                lsq[jj]  += __shfl_xor_sync(0xffffffffu, lsq[jj], o);
            }
        }
        if (lane == 0) {
#pragma unroll
            for (int jj = 0; jj < GJ; jj++) {
                sStg[(warp * GJ + jj) * 4 + 0] = lmax[jj];
                sStg[(warp * GJ + jj) * 4 + 1] = lmin[jj];
                sStg[(warp * GJ + jj) * 4 + 2] = lsum[jj];
                sStg[(warp * GJ + jj) * 4 + 3] = lsq[jj];
            }
        }
        __syncthreads();
        if (tid < GJ) {
            float mx = NEG_INF, mn = POS_INF, s = 0.f, s2 = 0.f;
            for (int w = 0; w < NTH / 32; w++) {
                mx = fmaxf(mx, sStg[(w * GJ + tid) * 4 + 0]);
                mn = fminf(mn, sStg[(w * GJ + tid) * 4 + 1]);
                s += sStg[(w * GJ + tid) * 4 + 2];
                s2 += sStg[(w * GJ + tid) * 4 + 3];
            }
            sXmax[tid]  = mx;
            sXmin[tid]  = mn;
            sXsum[tid]  = s;
            sXsq[tid]   = s2;
            sVmean[tid] = fmaf(sC[4], s * invL, sC[5]);
        }
        __syncthreads();
    }

    // ---------------- S2: sparsity measure M (sign-folded, idx prefetch) ----
    {
        const float Wq = sC[0], bq = sC[1], Wk = sC[2], bk = sC[3];
        // prefetch first two idx quads of iteration 0
        int4 pf0 = __ldg(&isampT[0 * L_ + tid]);
        int4 pf1 = __ldg(&isampT[1 * L_ + tid]);
#pragma unroll
        for (int i = 0; i < L_ / NTH; i++) {
            int l = tid + i * NTH;
            float4 xc = xs4[l];
            const float q0 = fmaf(Wq, xc.x, bq), q1 = fmaf(Wq, xc.y, bq);
            const float q2 = fmaf(Wq, xc.z, bq), q3 = fmaf(Wq, xc.w, bq);
            const float2 A01 = make_float2(q0 * Wk, q1 * Wk);
            const float2 A23 = make_float2(q2 * Wk, q3 * Wk);
            const float B00 = q0 * bk, B01 = q1 * bk, B02 = q2 * bk, B03 = q3 * bk;

            float gm0 = NEG_INF, gm1 = NEG_INF, gm2 = NEG_INF, gm3 = NEG_INF;
            float2 gs01 = make_float2(0.f, 0.f), gs23 = make_float2(0.f, 0.f);
            int4 iv0 = pf0, iv1 = pf1;
#pragma unroll
            for (int q = 0; q < U_ / 4; q += 2) {
                // issue the next pair of idx loads before consuming current
                int4 nx0, nx1;
                if (q + 2 < U_ / 4) {
                    nx0 = __ldg(&isampT[(q + 2) * L_ + l]);
                    nx1 = __ldg(&isampT[(q + 3) * L_ + l]);
                } else if (i + 1 < L_ / NTH) {
                    nx0 = __ldg(&isampT[0 * L_ + (l + NTH)]);
                    nx1 = __ldg(&isampT[1 * L_ + (l + NTH)]);
                } else {
                    nx0 = iv0; nx1 = iv1;
                }
                GATH4(iv0.x) GATH4(iv0.y) GATH4(iv0.z) GATH4(iv0.w)
                GATH4(iv1.x) GATH4(iv1.y) GATH4(iv1.z) GATH4(iv1.w)
                iv0 = nx0; iv1 = nx1;
            }
            pf0 = iv0; pf1 = iv1;   // carried into next l-iteration
            Msm[0 * L_ + l] = (gm0 + B00) - fmaf(A01.x, gs01.x, (float)U_ * B00) * invL;
            Msm[1 * L_ + l] = (gm1 + B01) - fmaf(A01.y, gs01.y, (float)U_ * B01) * invL;
            Msm[2 * L_ + l] = (gm2 + B02) - fmaf(A23.x, gs23.x, (float)U_ * B02) * invL;
            Msm[3 * L_ + l] = (gm3 + B03) - fmaf(A23.y, gs23.y, (float)U_ * B03) * invL;
        }
    }
    __syncthreads();

    // From here on: 128-thread groups (batch j) are independent.

    // ---------------- S3: top-U, stripe top-2 cache + removal mask ----------
    {
        const float* Mj = Msm + j * L_;
        float v0 = NEG_INF, v1 = NEG_INF;
        int i0 = 0, i1 = 0;
        unsigned rm = 0;
#pragma unroll
        for (int i = 0; i < 16; i++) {
            int l = t128 + (i << 7);
            float m = Mj[l];
            if (m > v0) { v1 = v0; i1 = i0; v0 = m; i0 = l; }
            else if (m > v1) { v1 = m; i1 = l; }
        }
        for (int it = 0; it < U_; it++) {
            float bvv = v0; int bi = i0;
#pragma unroll
            for (int o = 16; o; o >>= 1) {
                float ov = __shfl_xor_sync(0xffffffffu, bvv, o);
                int   oi = __shfl_xor_sync(0xffffffffu, bi, o);
                if (ov > bvv || (ov == bvv && oi < bi)) { bvv = ov; bi = oi; }
            }
            const int p = it & 1;
            const int sb = (j * 2 + p) * 4;
            if (lane == 0) { slotV[sb + wig] = bvv; slotI[sb + wig] = bi; }
            group_bar(j);
            float gv = slotV[sb + 0]; int gi = slotI[sb + 0];
#pragma unroll
            for (int w = 1; w < 4; w++) {
                float wv = slotV[sb + w]; int wi = slotI[sb + w];
                if (wv > gv || (wv == gv && wi < gi)) { gv = wv; gi = wi; }
            }
            if (t128 == 0) sTop[j * U_ + it] = gi;
            if ((gi & 127) == t128) {
                rm |= 1u << (gi >> 7);
                v0 = v1; i0 = i1; v1 = NEG_INF; i1 = 0;
                if (v0 == NEG_INF) {   // cache exhausted: rescan unmasked
                    for (int i = 0; i < 16; i++) {
                        if (!(rm & (1u << i))) {
                            int l = t128 + (i << 7);
                            float m = Mj[l];
                            if (m > v0) { v1 = v0; i1 = i0; v0 = m; i0 = l; }
                            else if (m > v1) { v1 = m; i1 = l; }
                        }
                    }
                }
            }
        }
        group_bar(j);
    }

    // ---------------- S3b: re-materialize contiguous batch column -----------
    float* xcj = Msm + j * L_;
    {
#pragma unroll
        for (int i = 0; i < 16; i++) {
            int l = t128 + (i << 7);
            xcj[l] = xsf[l * 4 + j];
        }
        group_bar(j);
    }

    // ---------------- S4: attention rows (fp32 exps, LDS.64 reads) ----------
    {
        const float Wq = sC[0], bq = sC[1], Wk = sC[2];
        const float Wv = sC[4], bvc = sC[5];
        const float xmx = sXmax[j], xmn = sXmin[j];
        const float LOG2E = 1.4426950408889634f;
        const float2* xc2 = (const float2*)xcj;
#pragma unroll
        for (int ch = 0; ch < 2; ch++) {
            const int ub = wig * 10 + ch * 5;
            float a2[5], m2n[5];
#pragma unroll
            for (int u = 0; u < 5; u++) {
                int t = sTop[j * U_ + ub + u];
                float qt = fmaf(Wq, xcj[t], bq);
                float a = qt * Wk;
                a2[u] = a * LOG2E;
                m2n[u] = -(a2[u] * ((a >= 0.f) ? xmx : xmn));
            }
            const float2 a01 = make_float2(a2[0], a2[1]);
            const float2 a23 = make_float2(a2[2], a2[3]);
            const float2 mn01 = make_float2(m2n[0], m2n[1]);
            const float2 mn23 = make_float2(m2n[2], m2n[3]);
            float2 s01 = make_float2(0.f, 0.f), s23 = s01, sv01 = s01, sv23 = s01;
            float s4 = 0.f, sv4 = 0.f;
#pragma unroll 4
            for (int i = 0; i < L_ / 64; i++) {
                float2 xp = xc2[lane + i * 32];   // LDS.64, conflict-free
                S4BODY(xp.x)
                S4BODY(xp.y)
            }
            float s[5]  = {s01.x, s01.y, s23.x, s23.y, s4};
            float sv[5] = {sv01.x, sv01.y, sv23.x, sv23.y, sv4};
#pragma unroll
            for (int u = 0; u < 5; u++) {
#pragma unroll
                for (int o = 16; o; o >>= 1) {
                    s[u]  += __shfl_xor_sync(0xffffffffu, s[u], o);
                    sv[u] += __shfl_xor_sync(0xffffffffu, sv[u], o);
                }
                if (lane == 0) sUpd[j * U_ + ub + u] = fmaf(Wv, sv[u] / s[u], bvc);
            }
        }
        group_bar(j);
    }

    // ---------------- S5: fixups + analytic LN1 -> GELU MLP -> LN2 ----------
    {
        const float Wo = sC[6], bo = sC[7];
        const float vm = sVmean[j];
        const float K0 = fmaf(Wo, vm, bo);

        // fixups at top indices; accumulate correction sums D1, D2
        float d1 = 0.f, d2 = 0.f;
        if (t128 < U_) {
            int l = sTop[j * U_ + t128];
            float xold = xcj[l];
            float d = Wo * (sUpd[j * U_ + t128] - vm);
            xcj[l] = xold + d;
            d1 = d;
            d2 = d * (2.f * (xold + K0) + d);
        }
#pragma unroll
        for (int o = 16; o; o >>= 1) {
            d1 += __shfl_xor_sync(0xffffffffu, d1, o);
            d2 += __shfl_xor_sync(0xffffffffu, d2, o);
        }
        if (lane == 0) { sR5[j * 16 + wig * 2] = d1; sR5[j * 16 + wig * 2 + 1] = d2; }
        group_bar(j);
        const float D1 = sR5[j * 16 + 0] + sR5[j * 16 + 2] + sR5[j * 16 + 4] + sR5[j * 16 + 6];
        const float D2 = sR5[j * 16 + 1] + sR5[j * 16 + 3] + sR5[j * 16 + 5] + sR5[j * 16 + 7];

        // analytic LN1 stats: z = x + K0 (+ fixups)
        const float Sx  = sXsum[j];
        const float Sx2 = sXsq[j];
        const float mean = (Sx + (float)L_ * K0 + D1) * invL;
        const float Szz  = Sx2 + 2.f * K0 * Sx + (float)L_ * K0 * K0 + D2;
        const float rstd = rsqrtf(Szz * invL - mean * mean + 1e-5f);
        const float meanAdj = mean - K0;   // z - mean == xcj - meanAdj

        const float w1 = sC[8], b1 = sC[9], w2 = sC[10], b2 = sC[11];
        const float g1 = sC[12], be1 = sC[13];
        float t1 = 0.f, t2 = 0.f;
#pragma unroll 4
        for (int i = 0; i < 16; i++) {
            int l = t128 + (i << 7);
            float x1v = fmaf((xcj[l] - meanAdj) * rstd, g1, be1);
            float yv  = fmaf(w1, x1v, b1);
            float ge  = 0.5f * yv * (1.0f + erff(yv * 0.70710678118654752f));
            float h   = x1v + fmaf(w2, ge, b2);
            xcj[l] = h;
            t1 += h; t2 = fmaf(h, h, t2);
        }
#pragma unroll
        for (int o = 16; o; o >>= 1) {
            t1 += __shfl_xor_sync(0xffffffffu, t1, o);
            t2 += __shfl_xor_sync(0xffffffffu, t2, o);
        }
        if (lane == 0) { sR5[j * 16 + 8 + wig * 2] = t1; sR5[j * 16 + 9 + wig * 2] = t2; }
        group_bar(j);
        t1 = sR5[j * 16 + 8]  + sR5[j * 16 + 10] + sR5[j * 16 + 12] + sR5[j * 16 + 14];
        t2 = sR5[j * 16 + 9]  + sR5[j * 16 + 11] + sR5[j * 16 + 13] + sR5[j * 16 + 15];
        float mean2 = t1 * invL;
        float rstd2 = rsqrtf(t2 * invL - mean2 * mean2 + 1e-5f);

        const float g2 = sC[14], be2 = sC[15];
        float* orow = outT + ((size_t)(b0 + j) * C_ + c) * L_;
#pragma unroll
        for (int i = 0; i < 16; i++) {
            int l = t128 + (i << 7);
            orow[l] = fmaf((xcj[l] - mean2) * rstd2, g2, be2);
        }
    }
}

extern "C" void kernel_launch(void* const* d_in, const int* in_sizes, int n_in,
                              void* d_out, int out_size) {
    const float* x = (const float*)d_in[0];
    const int* isamp = (const int*)d_in[17];
    float* out = (float*)d_out;

    float *xT = nullptr, *oT = nullptr;
    int4* iT = nullptr;
    cudaGetSymbolAddress((void**)&xT, g_xT);
    cudaGetSymbolAddress((void**)&oT, g_outT);
    cudaGetSymbolAddress((void**)&iT, g_isampT);

    cudaFuncSetAttribute(informer_main, cudaFuncAttributeMaxDynamicSharedMemorySize,
                         (int)SMEM_BYTES);

    dim3 tb4(8, 32);
    // main at launch index 3 (ncu skip=3 lands on it)
    transpose4_k<<<dim3(C_ / 32, L_ / 32, B_), tb4>>>(xT, x, L_, C_); // 0
    transpose_idx<<<L_ / 256, 256>>>(iT, isamp);                      // 1
    dummy_k<<<1, 32>>>();                                             // 2

    informer_main<<<dim3(C_, B_ / GJ), NTH, SMEM_BYTES>>>(            // 3
        xT, oT, iT,
        (const float*)d_in[1],  (const float*)d_in[2],  (const float*)d_in[3],  (const float*)d_in[4],
        (const float*)d_in[5],  (const float*)d_in[6],  (const float*)d_in[7],  (const float*)d_in[8],
        (const float*)d_in[9],  (const float*)d_in[10], (const float*)d_in[11], (const float*)d_in[12],
        (const float*)d_in[13], (const float*)d_in[14], (const float*)d_in[15], (const float*)d_in[16]);

    transpose4_k<<<dim3(L_ / 32, C_ / 32, B_), tb4>>>(out, oT, C_, L_); // 4
}

// round 15
// speedup vs baseline: 1.5051x; 1.1237x over previous
#include <cuda_runtime.h>
#include <cstdint>
#include <cstddef>

#define B_  16
#define L_  2048
#define C_  128
#define U_  40
#define GJ  4
#define NTH 512

#define NEG_INF __int_as_float(0xff800000)
#define POS_INF __int_as_float(0x7f800000)

// scratch (device globals: no allocation allowed)
__device__ float g_xT[B_ * C_ * L_];
__device__ float g_outT[B_ * C_ * L_];
__device__ int4  g_isampT[(U_ / 4) * L_];   // [q][l]

// ---------------------------------------------------------------------------
// float4 batched transpose: src (NI, NJ) -> dst (NJ, NI), per batch z.
__global__ void transpose4_k(float* __restrict__ dst, const float* __restrict__ src,
                             int NI, int NJ) {
    __shared__ float tile[32][33];
    const int z = blockIdx.z;
    const float* s = src + (size_t)z * NI * NJ;
    float* d = dst + (size_t)z * NI * NJ;
    const int j0 = blockIdx.x * 32, i0 = blockIdx.y * 32;
    const int tx = threadIdx.x, ty = threadIdx.y;
    float4 v = *(const float4*)&s[(size_t)(i0 + ty) * NJ + j0 + tx * 4];
    tile[ty][tx * 4 + 0] = v.x;
    tile[ty][tx * 4 + 1] = v.y;
    tile[ty][tx * 4 + 2] = v.z;
    tile[ty][tx * 4 + 3] = v.w;
    __syncthreads();
    float4 o;
    o.x = tile[tx * 4 + 0][ty];
    o.y = tile[tx * 4 + 1][ty];
    o.z = tile[tx * 4 + 2][ty];
    o.w = tile[tx * 4 + 3][ty];
    *(float4*)&d[(size_t)(j0 + ty) * NI + i0 + tx * 4] = o;
}

// isamp (L x U ints) -> isampT[q][l] (10 x 2048 int4)
__global__ void transpose_idx(int4* __restrict__ dst, const int* __restrict__ src) {
    __shared__ int4 st[256 * (U_ / 4)];
    const int lb = blockIdx.x * 256;
    const int4* s = (const int4*)(src + (size_t)lb * U_);
    for (int i = threadIdx.x; i < 256 * (U_ / 4); i += 256) st[i] = s[i];
    __syncthreads();
#pragma unroll
    for (int q = 0; q < U_ / 4; q++)
        dst[q * L_ + lb + threadIdx.x] = st[threadIdx.x * (U_ / 4) + q];
}

__global__ void dummy_k() {}

__device__ __forceinline__ float fexp2(float x) {
    float y;
    asm("ex2.approx.ftz.f32 %0, %1;" : "=f"(y) : "f"(x));
    return y;
}

// ordered-uint key: float order == unsigned order; 0 is below every real key
__device__ __forceinline__ unsigned fkey(float f) {
    unsigned u = __float_as_uint(f);
    return u ^ (unsigned)(((int)u >> 31) | 0x80000000);
}
__device__ __forceinline__ unsigned redux_max_u32(unsigned v) {
    unsigned r;
    asm("redux.sync.max.u32 %0, %1, 0xffffffff;" : "=r"(r) : "r"(v));
    return r;
}
__device__ __forceinline__ unsigned redux_min_u32(unsigned v) {
    unsigned r;
    asm("redux.sync.min.u32 %0, %1, 0xffffffff;" : "=r"(r) : "r"(v));
    return r;
}

// ---- Blackwell packed f32x2 ops ---------------------------------------------
__device__ __forceinline__ float2 f2mul(float2 a, float2 b) {
    float2 r;
    asm("{\n\t.reg .b64 ra, rb, rc;\n\t"
        "mov.b64 ra, {%2, %3};\n\t"
        "mov.b64 rb, {%4, %5};\n\t"
        "mul.rn.f32x2 rc, ra, rb;\n\t"
        "mov.b64 {%0, %1}, rc;\n\t}"
        : "=f"(r.x), "=f"(r.y) : "f"(a.x), "f"(a.y), "f"(b.x), "f"(b.y));
    return r;
}
__device__ __forceinline__ float2 f2add(float2 a, float2 b) {
    float2 r;
    asm("{\n\t.reg .b64 ra, rb, rc;\n\t"
        "mov.b64 ra, {%2, %3};\n\t"
        "mov.b64 rb, {%4, %5};\n\t"
        "add.rn.f32x2 rc, ra, rb;\n\t"
        "mov.b64 {%0, %1}, rc;\n\t}"
        : "=f"(r.x), "=f"(r.y) : "f"(a.x), "f"(a.y), "f"(b.x), "f"(b.y));
    return r;
}
__device__ __forceinline__ float2 f2fma(float2 a, float2 b, float2 c) {
    float2 r;
    asm("{\n\t.reg .b64 ra, rb, rc, rd;\n\t"
        "mov.b64 ra, {%2, %3};\n\t"
        "mov.b64 rb, {%4, %5};\n\t"
        "mov.b64 rc, {%6, %7};\n\t"
        "fma.rn.f32x2 rd, ra, rb, rc;\n\t"
        "mov.b64 {%0, %1}, rd;\n\t}"
        : "=f"(r.x), "=f"(r.y)
        : "f"(a.x), "f"(a.y), "f"(b.x), "f"(b.y), "f"(c.x), "f"(c.y));
    return r;
}

__device__ __forceinline__ void group_bar(int j) {
    asm volatile("bar.sync %0, 128;" :: "r"(j + 1) : "memory");
}

// shared layout (floats)
static constexpr int SM_XS4   = 0;                    // 4L: float4 xs4[l]
static constexpr int SM_MSM   = SM_XS4 + 4 * L_;      // 4L: M[j*L+l]; later xc[j*L+l]
static constexpr int SM_XMAX  = SM_MSM + GJ * L_;
static constexpr int SM_XMIN  = SM_XMAX + 4;
static constexpr int SM_VMEAN = SM_XMIN + 4;
static constexpr int SM_XSUM  = SM_VMEAN + 4;
static constexpr int SM_XSQ   = SM_XSUM + 4;
static constexpr int SM_UPD   = SM_XSQ + 4;
static constexpr int SM_TOP   = SM_UPD + GJ * U_;
static constexpr int SM_STAGE = SM_TOP + GJ * U_;     // 256
static constexpr int SM_SLOTV = SM_STAGE + 256;       // 32 (unsigned keys)
static constexpr int SM_SLOTI = SM_SLOTV + 32;        // 32
static constexpr int SM_R5    = SM_SLOTI + 32;        // 64
static constexpr int SM_CONST = SM_R5 + 64;           // 16
static constexpr int SM_FLOATS_TOTAL = SM_CONST + 16;
static constexpr size_t SMEM_BYTES = (size_t)SM_FLOATS_TOTAL * 4;

#define GATH4(ii)                                                     \
    {                                                                 \
        float4 g = xs4[ii];                                           \
        float2 t01 = f2mul(A01, make_float2(g.x, g.y));               \
        float2 t23 = f2mul(A23, make_float2(g.z, g.w));               \
        gm0 = fmaxf(gm0, t01.x); gm1 = fmaxf(gm1, t01.y);             \
        gm2 = fmaxf(gm2, t23.x); gm3 = fmaxf(gm3, t23.y);             \
        gs01 = f2add(gs01, make_float2(g.x, g.y));                    \
        gs23 = f2add(gs23, make_float2(g.z, g.w));                    \
    }

// inner S4 body for one x value (fp32 MUFU exps)
#define S4BODY(xv)                                                    \
    {                                                                 \
        float2 xv2 = make_float2((xv), (xv));                         \
        float2 p01 = f2fma(a01, xv2, mn01);                           \
        float2 p23 = f2fma(a23, xv2, mn23);                           \
        float p4 = fmaf(a2[4], (xv), m2n[4]);                         \
        float2 e01 = make_float2(fexp2(p01.x), fexp2(p01.y));         \
        float2 e23 = make_float2(fexp2(p23.x), fexp2(p23.y));         \
        float e4 = fexp2(p4);                                         \
        s01 = f2add(s01, e01);                                        \
        s23 = f2add(s23, e23);                                        \
        s4 += e4;                                                     \
        sv01 = f2fma(e01, xv2, sv01);                                 \
        sv23 = f2fma(e23, xv2, sv23);                                 \
        sv4 = fmaf(e4, (xv), sv4);                                    \
    }

// top-2 key-cache insert (strict > keeps earlier/smaller l on ties)
#define T2INS(k, l)                                                   \
    if ((k) > k0) { k1 = k0; i1 = i0; k0 = (k); i0 = (l); }           \
    else if ((k) > k1) { k1 = (k); i1 = (l); }

__global__ void __launch_bounds__(NTH, 3)
informer_main(const float* __restrict__ xT, float* __restrict__ outT,
              const int4* __restrict__ isampT,
              const float* pWq, const float* pbq, const float* pWk, const float* pbk,
              const float* pWv, const float* pbv, const float* pWo, const float* pbo,
              const float* pw1, const float* pb1, const float* pw2, const float* pb2,
              const float* pg1, const float* pbe1, const float* pg2, const float* pbe2) {
    const int c    = blockIdx.x;
    const int b0   = blockIdx.y * GJ;
    const int tid  = threadIdx.x;
    const int lane = tid & 31, warp = tid >> 5;
    const int j    = warp >> 2;        // batch group (128 threads each)
    const int t128 = tid & 127;
    const int wig  = warp & 3;

    extern __shared__ float sm[];
    float4* xs4  = (float4*)(sm + SM_XS4);
    float*  xsf  = sm + SM_XS4;
    float*  Msm  = sm + SM_MSM;
    float* sXmax = sm + SM_XMAX;
    float* sXmin = sm + SM_XMIN;
    float* sVmean= sm + SM_VMEAN;
    float* sXsum = sm + SM_XSUM;
    float* sXsq  = sm + SM_XSQ;
    float* sUpd  = sm + SM_UPD;
    int*   sTop  = (int*)(sm + SM_TOP);
    float* sStg  = sm + SM_STAGE;
    unsigned* slotK = (unsigned*)(sm + SM_SLOTV);
    int*   slotI = (int*)(sm + SM_SLOTI);
    float* sR5   = sm + SM_R5;
    float* sC    = sm + SM_CONST;

    if (tid == 0) {
        sC[0]=*pWq; sC[1]=*pbq; sC[2]=*pWk;  sC[3]=*pbk;
        sC[4]=*pWv; sC[5]=*pbv; sC[6]=*pWo;  sC[7]=*pbo;
        sC[8]=*pw1; sC[9]=*pb1; sC[10]=*pw2; sC[11]=*pb2;
        sC[12]=*pg1; sC[13]=*pbe1; sC[14]=*pg2; sC[15]=*pbe2;
    }
    const float invL = 1.0f / (float)L_;

    // ---------------- S1: load columns -> float4 interleaved, stats ---------
    {
        float v[GJ][L_ / NTH];
        float lmax[GJ], lmin[GJ], lsum[GJ], lsq[GJ];
#pragma unroll
        for (int jj = 0; jj < GJ; jj++) {
            lmax[jj] = NEG_INF; lmin[jj] = POS_INF; lsum[jj] = 0.f; lsq[jj] = 0.f;
            const float* row = xT + ((size_t)(b0 + jj) * C_ + c) * L_;
#pragma unroll
            for (int i = 0; i < L_ / NTH; i++) {
                float x = row[tid + i * NTH];
                v[jj][i] = x;
                lmax[jj] = fmaxf(lmax[jj], x);
                lmin[jj] = fminf(lmin[jj], x);
                lsum[jj] += x;
                lsq[jj] = fmaf(x, x, lsq[jj]);
            }
        }
#pragma unroll
        for (int i = 0; i < L_ / NTH; i++)
            xs4[tid + i * NTH] = make_float4(v[0][i], v[1][i], v[2][i], v[3][i]);
#pragma unroll
        for (int jj = 0; jj < GJ; jj++) {
#pragma unroll
            for (int o = 16; o; o >>= 1) {
                lmax[jj] = fmaxf(lmax[jj], __shfl_xor_sync(0xffffffffu, lmax[jj], o));
                lmin[jj] = fminf(lmin[jj], __shfl_xor_sync(0xffffffffu, lmin[jj], o));
                lsum[jj] += __shfl_xor_sync(0xffffffffu, lsum[jj], o);
                lsq[jj]  += __shfl_xor_sync(0xffffffffu, lsq[jj], o);
            }
        }
        if (lane == 0) {
#pragma unroll
            for (int jj = 0; jj < GJ; jj++) {
                sStg[(warp * GJ + jj) * 4 + 0] = lmax[jj];
                sStg[(warp * GJ + jj) * 4 + 1] = lmin[jj];
                sStg[(warp * GJ + jj) * 4 + 2] = lsum[jj];
                sStg[(warp * GJ + jj) * 4 + 3] = lsq[jj];
            }
        }
        __syncthreads();
        if (tid < GJ) {
            float mx = NEG_INF, mn = POS_INF, s = 0.f, s2 = 0.f;
            for (int w = 0; w < NTH / 32; w++) {
                mx = fmaxf(mx, sStg[(w * GJ + tid) * 4 + 0]);
                mn = fminf(mn, sStg[(w * GJ + tid) * 4 + 1]);
                s += sStg[(w * GJ + tid) * 4 + 2];
                s2 += sStg[(w * GJ + tid) * 4 + 3];
            }
            sXmax[tid]  = mx;
            sXmin[tid]  = mn;
            sXsum[tid]  = s;
            sXsq[tid]   = s2;
            sVmean[tid] = fmaf(sC[4], s * invL, sC[5]);
        }
        __syncthreads();
    }

    // ---------------- S2: sparsity measure M (sign-folded, f32x2) -----------
    {
        const float Wq = sC[0], bq = sC[1], Wk = sC[2], bk = sC[3];
#pragma unroll
        for (int i = 0; i < L_ / NTH; i++) {
            int l = tid + i * NTH;
            float4 xc = xs4[l];
            const float q0 = fmaf(Wq, xc.x, bq), q1 = fmaf(Wq, xc.y, bq);
            const float q2 = fmaf(Wq, xc.z, bq), q3 = fmaf(Wq, xc.w, bq);
            const float2 A01 = make_float2(q0 * Wk, q1 * Wk);
            const float2 A23 = make_float2(q2 * Wk, q3 * Wk);
            const float B00 = q0 * bk, B01 = q1 * bk, B02 = q2 * bk, B03 = q3 * bk;

            float gm0 = NEG_INF, gm1 = NEG_INF, gm2 = NEG_INF, gm3 = NEG_INF;
            float2 gs01 = make_float2(0.f, 0.f), gs23 = make_float2(0.f, 0.f);
#pragma unroll
            for (int q = 0; q < U_ / 4; q++) {
                int4 iv = __ldg(&isampT[q * L_ + l]);
                GATH4(iv.x) GATH4(iv.y) GATH4(iv.z) GATH4(iv.w)
            }
            Msm[0 * L_ + l] = (gm0 + B00) - fmaf(A01.x, gs01.x, (float)U_ * B00) * invL;
            Msm[1 * L_ + l] = (gm1 + B01) - fmaf(A01.y, gs01.y, (float)U_ * B01) * invL;
            Msm[2 * L_ + l] = (gm2 + B02) - fmaf(A23.x, gs23.x, (float)U_ * B02) * invL;
            Msm[3 * L_ + l] = (gm3 + B03) - fmaf(A23.y, gs23.y, (float)U_ * B03) * invL;
        }
    }
    __syncthreads();

    // From here on: 128-thread groups (batch j) are independent.

    // ---------------- S3: top-U via REDUX argmax (4 warps per group) --------
    {
        const float* Mj = Msm + j * L_;
        unsigned k0 = 0, k1 = 0;   // ordered keys (0 = empty; real keys > fkey(-inf) > 0)
        int i0 = 0, i1 = 0;
        unsigned rm = 0;
#pragma unroll
        for (int i = 0; i < 16; i++) {
            int l = t128 + (i << 7);
            unsigned k = fkey(Mj[l]);
            T2INS(k, l)
        }
        for (int it = 0; it < U_; it++) {
            // warp argmax: 2 REDUX ops instead of 10 SHFLs
            unsigned wk = redux_max_u32(k0);
            unsigned cand = (k0 == wk) ? (unsigned)i0 : 0xFFFFFFFFu;
            unsigned wi = redux_min_u32(cand);
            const int p = it & 1;
            const int sb = (j * 2 + p) * 4;
            if (lane == 0) { slotK[sb + wig] = wk; slotI[sb + wig] = (int)wi; }
            group_bar(j);
            unsigned gk = slotK[sb + 0]; int gi = slotI[sb + 0];
#pragma unroll
            for (int w = 1; w < 4; w++) {
                unsigned k2 = slotK[sb + w]; int i2 = slotI[sb + w];
                if (k2 > gk || (k2 == gk && i2 < gi)) { gk = k2; gi = i2; }
            }
            if (t128 == 0) sTop[j * U_ + it] = gi;
            if (k0 == wk && i0 == gi) {   // unique owner thread
                rm |= 1u << (gi >> 7);
                k0 = k1; i0 = i1; k1 = 0; i1 = 0;
                if (k0 == 0) {   // cache exhausted: rescan unmasked
                    for (int i = 0; i < 16; i++) {
                        if (!(rm & (1u << i))) {
                            int l = t128 + (i << 7);
                            unsigned k = fkey(Mj[l]);
                            T2INS(k, l)
                        }
                    }
                }
            }
        }
        group_bar(j);
    }

    // ---------------- S3b: re-materialize contiguous batch column -----------
    float* xcj = Msm + j * L_;
    {
#pragma unroll
        for (int i = 0; i < 16; i++) {
            int l = t128 + (i << 7);
            xcj[l] = xsf[l * 4 + j];
        }
        group_bar(j);
    }

    // ---------------- S4: attention rows (fp32 exps, LDS.64 reads) ----------
    {
        const float Wq = sC[0], bq = sC[1], Wk = sC[2];
        const float Wv = sC[4], bvc = sC[5];
        const float xmx = sXmax[j], xmn = sXmin[j];
        const float LOG2E = 1.4426950408889634f;
        const float2* xc2 = (const float2*)xcj;
#pragma unroll
        for (int ch = 0; ch < 2; ch++) {
            const int ub = wig * 10 + ch * 5;
            float a2[5], m2n[5];
#pragma unroll
            for (int u = 0; u < 5; u++) {
                int t = sTop[j * U_ + ub + u];
                float qt = fmaf(Wq, xcj[t], bq);
                float a = qt * Wk;
                a2[u] = a * LOG2E;
                m2n[u] = -(a2[u] * ((a >= 0.f) ? xmx : xmn));
            }
            const float2 a01 = make_float2(a2[0], a2[1]);
            const float2 a23 = make_float2(a2[2], a2[3]);
            const float2 mn01 = make_float2(m2n[0], m2n[1]);
            const float2 mn23 = make_float2(m2n[2], m2n[3]);
            float2 s01 = make_float2(0.f, 0.f), s23 = s01, sv01 = s01, sv23 = s01;
            float s4 = 0.f, sv4 = 0.f;
#pragma unroll 4
            for (int i = 0; i < L_ / 64; i++) {
                float2 xp = xc2[lane + i * 32];   // LDS.64, conflict-free
                S4BODY(xp.x)
                S4BODY(xp.y)
            }
            float s[5]  = {s01.x, s01.y, s23.x, s23.y, s4};
            float sv[5] = {sv01.x, sv01.y, sv23.x, sv23.y, sv4};
#pragma unroll
            for (int u = 0; u < 5; u++) {
#pragma unroll
                for (int o = 16; o; o >>= 1) {
                    s[u]  += __shfl_xor_sync(0xffffffffu, s[u], o);
                    sv[u] += __shfl_xor_sync(0xffffffffu, sv[u], o);
                }
                if (lane == 0) sUpd[j * U_ + ub + u] = fmaf(Wv, sv[u] / s[u], bvc);
            }
        }
        group_bar(j);
    }

    // ---------------- S5: fixups + analytic LN1 -> GELU MLP -> LN2 ----------
    {
        const float Wo = sC[6], bo = sC[7];
        const float vm = sVmean[j];
        const float K0 = fmaf(Wo, vm, bo);

        // fixups at top indices; accumulate correction sums D1, D2
        float d1 = 0.f, d2 = 0.f;
        if (t128 < U_) {
            int l = sTop[j * U_ + t128];
            float xold = xcj[l];
            float d = Wo * (sUpd[j * U_ + t128] - vm);
            xcj[l] = xold + d;
            d1 = d;
            d2 = d * (2.f * (xold + K0) + d);
        }
#pragma unroll
        for (int o = 16; o; o >>= 1) {
            d1 += __shfl_xor_sync(0xffffffffu, d1, o);
            d2 += __shfl_xor_sync(0xffffffffu, d2, o);
        }
        if (lane == 0) { sR5[j * 16 + wig * 2] = d1; sR5[j * 16 + wig * 2 + 1] = d2; }
        group_bar(j);
        const float D1 = sR5[j * 16 + 0] + sR5[j * 16 + 2] + sR5[j * 16 + 4] + sR5[j * 16 + 6];
        const float D2 = sR5[j * 16 + 1] + sR5[j * 16 + 3] + sR5[j * 16 + 5] + sR5[j * 16 + 7];

        // analytic LN1 stats: z = x + K0 (+ fixups)
        const float Sx  = sXsum[j];
        const float Sx2 = sXsq[j];
        const float mean = (Sx + (float)L_ * K0 + D1) * invL;
        const float Szz  = Sx2 + 2.f * K0 * Sx + (float)L_ * K0 * K0 + D2;
        const float rstd = rsqrtf(Szz * invL - mean * mean + 1e-5f);
        const float meanAdj = mean - K0;   // z - mean == xcj - meanAdj

        const float w1 = sC[8], b1 = sC[9], w2 = sC[10], b2 = sC[11];
        const float g1 = sC[12], be1 = sC[13];
        float t1 = 0.f, t2 = 0.f;
#pragma unroll 4
        for (int i = 0; i < 16; i++) {
            int l = t128 + (i << 7);
            float x1v = fmaf((xcj[l] - meanAdj) * rstd, g1, be1);
            float yv  = fmaf(w1, x1v, b1);
            float ge  = 0.5f * yv * (1.0f + erff(yv * 0.70710678118654752f));
            float h   = x1v + fmaf(w2, ge, b2);
            xcj[l] = h;
            t1 += h; t2 = fmaf(h, h, t2);
        }
#pragma unroll
        for (int o = 16; o; o >>= 1) {
            t1 += __shfl_xor_sync(0xffffffffu, t1, o);
            t2 += __shfl_xor_sync(0xffffffffu, t2, o);
        }
        if (lane == 0) { sR5[j * 16 + 8 + wig * 2] = t1; sR5[j * 16 + 9 + wig * 2] = t2; }
        group_bar(j);
        t1 = sR5[j * 16 + 8]  + sR5[j * 16 + 10] + sR5[j * 16 + 12] + sR5[j * 16 + 14];
        t2 = sR5[j * 16 + 9]  + sR5[j * 16 + 11] + sR5[j * 16 + 13] + sR5[j * 16 + 15];
        float mean2 = t1 * invL;
        float rstd2 = rsqrtf(t2 * invL - mean2 * mean2 + 1e-5f);

        const float g2 = sC[14], be2 = sC[15];
        float* orow = outT + ((size_t)(b0 + j) * C_ + c) * L_;
#pragma unroll
        for (int i = 0; i < 16; i++) {
            int l = t128 + (i << 7);
            orow[l] = fmaf((xcj[l] - mean2) * rstd2, g2, be2);
        }
    }
}

extern "C" void kernel_launch(void* const* d_in, const int* in_sizes, int n_in,
                              void* d_out, int out_size) {
    const float* x = (const float*)d_in[0];
    const int* isamp = (const int*)d_in[17];
    float* out = (float*)d_out;

    float *xT = nullptr, *oT = nullptr;
    int4* iT = nullptr;
    cudaGetSymbolAddress((void**)&xT, g_xT);
    cudaGetSymbolAddress((void**)&oT, g_outT);
    cudaGetSymbolAddress((void**)&iT, g_isampT);

    cudaFuncSetAttribute(informer_main, cudaFuncAttributeMaxDynamicSharedMemorySize,
                         (int)SMEM_BYTES);

    dim3 tb4(8, 32);
    // main at launch index 3 (ncu skip=3 lands on it)
    transpose4_k<<<dim3(C_ / 32, L_ / 32, B_), tb4>>>(xT, x, L_, C_); // 0
    transpose_idx<<<L_ / 256, 256>>>(iT, isamp);                      // 1
    dummy_k<<<1, 32>>>();                                             // 2

    informer_main<<<dim3(C_, B_ / GJ), NTH, SMEM_BYTES>>>(            // 3
        xT, oT, iT,
        (const float*)d_in[1],  (const float*)d_in[2],  (const float*)d_in[3],  (const float*)d_in[4],
        (const float*)d_in[5],  (const float*)d_in[6],  (const float*)d_in[7],  (const float*)d_in[8],
        (const float*)d_in[9],  (const float*)d_in[10], (const float*)d_in[11], (const float*)d_in[12],
        (const float*)d_in[13], (const float*)d_in[14], (const float*)d_in[15], (const float*)d_in[16]);

    transpose4_k<<<dim3(L_ / 32, C_ / 32, B_), tb4>>>(out, oT, C_, L_); // 4
}